// round 17
// baseline (speedup 1.0000x reference)
#include <cuda_runtime.h>
#include <cuda_bf16.h>
#include <stdint.h>

#define BATCH 65536
#define VOCAB 1048576

// ---------------- device scratch (no allocation allowed) ----------------
__device__ uint16_t g_bufA_hi[BATCH * 1024];
__device__ uint16_t g_bufA_lo[BATCH * 1024];
__device__ uint16_t g_bufB_hi[BATCH * 1024];
__device__ uint16_t g_bufB_lo[BATCH * 1024];
__device__ uint16_t g_wt_hi[2408448];
__device__ uint16_t g_wt_lo[2408448];
__device__ float    g_fin[BATCH * 256];

// weight offsets (transposed [N,K], K padded to mult of 32):
#define OFF_BW0 0        // [512 ,  32]
#define OFF_BW1 16384    // [256 , 512]
#define OFF_BW2 147456   // [128 , 256]
#define OFF_TW0 180224   // [1024, 512]
#define OFF_TW1 704512   // [1024,1024]
#define OFF_TW2 1753088  // [512 ,1024]
#define OFF_TW3 2277376  // [256 , 512]   total 2408448

__device__ __forceinline__ void f2hilo(float x, uint16_t &hi, uint16_t &lo) {
    __nv_bfloat16 h = __float2bfloat16(x);
    float hf = __bfloat162float(h);
    __nv_bfloat16 l = __float2bfloat16(x - hf);
    hi = __bfloat16_as_ushort(h);
    lo = __bfloat16_as_ushort(l);
}
__device__ __forceinline__ float b2f(uint16_t u) {
    return __bfloat162float(__ushort_as_bfloat16(u));
}

// ---------------- PTX helpers ----------------
__device__ __forceinline__ uint32_t smem_u32(const void* p) {
    return (uint32_t)__cvta_generic_to_shared(p);
}
__device__ __forceinline__ void cp16(uint32_t s, const void* g) {
    asm volatile("cp.async.cg.shared.global [%0], [%1], 16;\n" :: "r"(s), "l"(g));
}
#define CP_COMMIT() asm volatile("cp.async.commit_group;\n" ::: "memory")
#define CP_WAIT0()  asm volatile("cp.async.wait_group 0;\n" ::: "memory")
#define CP_WAIT1()  asm volatile("cp.async.wait_group 1;\n" ::: "memory")

__device__ __forceinline__ void mma_bf16(float* c, const uint32_t* a, const uint32_t* b) {
    asm volatile(
        "mma.sync.aligned.m16n8k16.row.col.f32.bf16.bf16.f32 "
        "{%0,%1,%2,%3}, {%4,%5,%6,%7}, {%8,%9}, {%0,%1,%2,%3};\n"
        : "+f"(c[0]), "+f"(c[1]), "+f"(c[2]), "+f"(c[3])
        : "r"(a[0]), "r"(a[1]), "r"(a[2]), "r"(a[3]), "r"(b[0]), "r"(b[1]));
}
__device__ __forceinline__ void ldsm4(uint32_t* r, uint32_t addr) {
    asm volatile("ldmatrix.sync.aligned.m8n8.x4.shared.b16 {%0,%1,%2,%3}, [%4];\n"
                 : "=r"(r[0]), "=r"(r[1]), "=r"(r[2]), "=r"(r[3])
                 : "r"(addr));
}
// SW64 swizzle for 64-byte rows (GEMM tiles)
__device__ __forceinline__ uint32_t swz(uint32_t off) {
    return off ^ ((off >> 3) & 0x30);
}

// ---------------- dense input conversion ----------------
__global__ void conv_dense_kernel(const float* __restrict__ d,
                                  uint16_t* __restrict__ hi, uint16_t* __restrict__ lo) {
    int idx = blockIdx.x * blockDim.x + threadIdx.x;   // BATCH*32
    int b = idx >> 5, k = idx & 31;
    float v = (k < 13) ? d[b * 13 + k] : 0.f;
    uint16_t h, l;
    f2hilo(v, h, l);
    hi[idx] = h; lo[idx] = l;
}

// ---------------- fused weight transpose + hi/lo split (one launch) ----------
// 1184 blocks; block-range dispatch across the 7 weight regions.
__global__ void conv_wt_all(const float* __restrict__ w0, const float* __restrict__ w1,
                            const float* __restrict__ w2, const float* __restrict__ w3,
                            const float* __restrict__ w4, const float* __restrict__ w5,
                            const float* __restrict__ w6,
                            uint16_t* __restrict__ whi, uint16_t* __restrict__ wlo) {
    __shared__ float tile[32][65];
    int b = blockIdx.x;
    const float* W; int K, N, Kpad, off, nx;
    if      (b < 16)   { W = w0; K = 13;   N = 512;  Kpad = 32;   off = OFF_BW0; nx = 16; }
    else if (b < 80)   { W = w1; K = 512;  N = 256;  Kpad = 512;  off = OFF_BW1; nx = 8;  b -= 16; }
    else if (b < 96)   { W = w2; K = 256;  N = 128;  Kpad = 256;  off = OFF_BW2; nx = 4;  b -= 80; }
    else if (b < 352)  { W = w3; K = 506;  N = 1024; Kpad = 512;  off = OFF_TW0; nx = 32; b -= 96; }
    else if (b < 864)  { W = w4; K = 1024; N = 1024; Kpad = 1024; off = OFF_TW1; nx = 32; b -= 352; }
    else if (b < 1120) { W = w5; K = 1024; N = 512;  Kpad = 1024; off = OFF_TW2; nx = 16; b -= 864; }
    else               { W = w6; K = 512;  N = 256;  Kpad = 512;  off = OFF_TW3; nx = 8;  b -= 1120; }
    const int tx = threadIdx.x & 31;
    const int ty = threadIdx.x >> 5;
    const int n0 = (b % nx) * 32;
    const int k0 = (b / nx) * 64;
    uint16_t* hi = whi + off;
    uint16_t* lo = wlo + off;

#pragma unroll
    for (int kk = ty; kk < 64; kk += 8) {
        int k = k0 + kk, n = n0 + tx;
        tile[tx][kk] = (k < K) ? W[(size_t)k * N + n] : 0.f;
    }
    __syncthreads();

#pragma unroll
    for (int r = ty; r < 32; r += 8) {
        int n = n0 + r;
        int k = k0 + tx * 2;
        if (k < Kpad) {
            float v0 = tile[r][tx * 2], v1 = tile[r][tx * 2 + 1];
            uint16_t h0, l0, h1, l1;
            f2hilo(v0, h0, l0);
            f2hilo(v1, h1, l1);
            *(uint32_t*)&hi[(size_t)n * Kpad + k] = (uint32_t)h0 | ((uint32_t)h1 << 16);
            *(uint32_t*)&lo[(size_t)n * Kpad + k] = (uint32_t)l0 | ((uint32_t)l1 << 16);
        }
    }
}

// ---------------- bf16x3 GEMM (128x128, 2 CTA/SM, 3-stage, overlapped issue) --
// mode 0: bf16 hi/lo planes out.  mode 1: fp32 out (Ofp).
#define STAGE_B 32768          // Ah 8K | Al 8K | Bh 8K | Bl 8K
#define SOFF_AL 8192
#define SOFF_BH 16384
#define SOFF_BL 24576

__global__ __launch_bounds__(256, 2)
void gemm_hmma(const uint16_t* __restrict__ Ahi, const uint16_t* __restrict__ Alo,
               const uint16_t* __restrict__ Whi, const uint16_t* __restrict__ Wlo,
               const float* __restrict__ bias,
               uint16_t* __restrict__ Ohi, uint16_t* __restrict__ Olo,
               float* __restrict__ Ofp,
               int Nsz, int K, int relu, int mode) {
    extern __shared__ __align__(16) uint8_t dsm[];
    const uint32_t sbase = smem_u32(dsm);

    const int tid  = threadIdx.x;
    const int lane = tid & 31;
    const int warp = tid >> 5;
    const int wm = warp & 3;
    const int wn = warp >> 2;
    const size_t mBase = (size_t)blockIdx.y * 128;
    const int    nBase = blockIdx.x * 128;
    const int    nch   = K >> 5;

    const int r0 = tid >> 2, ch = tid & 3;
    const uint16_t* gp[4];
    gp[0] = Ahi + (mBase + r0) * (size_t)K + ch * 8;
    gp[1] = Alo + (mBase + r0) * (size_t)K + ch * 8;
    gp[2] = Whi + (size_t)(nBase + r0) * K + ch * 8;
    gp[3] = Wlo + (size_t)(nBase + r0) * K + ch * 8;
    const uint32_t soff = swz((uint32_t)r0 * 64 + ch * 16);
    const size_t rowD = (size_t)64 * K;

    auto issue = [&](int c) {
        const uint32_t st = sbase + (c % 3) * STAGE_B + soff;
        const int k0 = c << 5;
#pragma unroll
        for (int rg = 0; rg < 4; rg++) {
            cp16(st + rg * 8192,        gp[rg] + k0);
            cp16(st + rg * 8192 + 4096, gp[rg] + rowD + k0);
        }
    };

    float acc[2][8][4];
#pragma unroll
    for (int a = 0; a < 2; a++)
#pragma unroll
        for (int b = 0; b < 8; b++)
#pragma unroll
            for (int c = 0; c < 4; c++) acc[a][b][c] = 0.f;

    const uint32_t aRow = (uint32_t)(wm * 32 + (lane & 15)) * 64 + (lane >> 4) * 16;
    const uint32_t bRow = (uint32_t)(wn * 64 + (lane & 7) + ((lane >> 4) << 3)) * 64
                        + (((lane >> 3) & 1) << 4);

    issue(0); CP_COMMIT();
    if (nch > 1) { issue(1); CP_COMMIT(); }

    for (int c = 0; c < nch; c++) {
        if (c + 1 < nch) CP_WAIT1(); else CP_WAIT0();
        __syncthreads();

        const uint32_t st = sbase + (c % 3) * STAGE_B;
#pragma unroll
        for (int kk = 0; kk < 2; kk++) {
            uint32_t aH[2][4], aL[2][4], bB[4][4];
#pragma unroll
            for (int mt = 0; mt < 2; mt++) {
                uint32_t off = swz(aRow + mt * 16 * 64 + kk * 32);
                ldsm4(aH[mt], st + off);
                ldsm4(aL[mt], st + SOFF_AL + off);
            }
#pragma unroll
            for (int np = 0; np < 4; np++)
                ldsm4(bB[np], st + SOFF_BH + swz(bRow + np * 16 * 64 + kk * 32));

            // overlap next-next chunk's cp.async issue with this chunk's MMAs
            if (kk == 0 && c + 2 < nch) { issue(c + 2); CP_COMMIT(); }

#pragma unroll
            for (int np = 0; np < 4; np++)
#pragma unroll
                for (int mt = 0; mt < 2; mt++) {
                    mma_bf16(acc[mt][np * 2],     aH[mt], &bB[np][0]);
                    mma_bf16(acc[mt][np * 2 + 1], aH[mt], &bB[np][2]);
                }
#pragma unroll
            for (int np = 0; np < 4; np++) {
#pragma unroll
                for (int mt = 0; mt < 2; mt++) {
                    mma_bf16(acc[mt][np * 2],     aL[mt], &bB[np][0]);
                    mma_bf16(acc[mt][np * 2 + 1], aL[mt], &bB[np][2]);
                }
                ldsm4(bB[np], st + SOFF_BL + swz(bRow + np * 16 * 64 + kk * 32));
            }
#pragma unroll
            for (int np = 0; np < 4; np++)
#pragma unroll
                for (int mt = 0; mt < 2; mt++) {
                    mma_bf16(acc[mt][np * 2],     aH[mt], &bB[np][0]);
                    mma_bf16(acc[mt][np * 2 + 1], aH[mt], &bB[np][2]);
                }
        }
    }

#pragma unroll
    for (int mt = 0; mt < 2; mt++) {
        size_t m0 = mBase + wm * 32 + mt * 16 + (lane >> 2);
#pragma unroll
        for (int nt = 0; nt < 8; nt++) {
            int n = nBase + wn * 64 + nt * 8 + (lane & 3) * 2;
            float b0 = bias[n], b1 = bias[n + 1];
            float v0 = acc[mt][nt][0] + b0;
            float v1 = acc[mt][nt][1] + b1;
            float v2 = acc[mt][nt][2] + b0;
            float v3 = acc[mt][nt][3] + b1;
            if (relu) {
                v0 = fmaxf(v0, 0.f); v1 = fmaxf(v1, 0.f);
                v2 = fmaxf(v2, 0.f); v3 = fmaxf(v3, 0.f);
            }
            if (mode) {
                *(float2*)&Ofp[m0 * Nsz + n]       = make_float2(v0, v1);
                *(float2*)&Ofp[(m0 + 8) * Nsz + n] = make_float2(v2, v3);
            } else {
                uint16_t h0, l0, h1, l1;
                f2hilo(v0, h0, l0); f2hilo(v1, h1, l1);
                *(uint32_t*)&Ohi[m0 * Nsz + n] = (uint32_t)h0 | ((uint32_t)h1 << 16);
                *(uint32_t*)&Olo[m0 * Nsz + n] = (uint32_t)l0 | ((uint32_t)l1 << 16);
                f2hilo(v2, h0, l0); f2hilo(v3, h1, l1);
                *(uint32_t*)&Ohi[(m0 + 8) * Nsz + n] = (uint32_t)h0 | ((uint32_t)h1 << 16);
                *(uint32_t*)&Olo[(m0 + 8) * Nsz + n] = (uint32_t)l0 | ((uint32_t)l1 << 16);
            }
        }
    }
}

// ---------------- interaction via HMMA gram (bf16x3), 1 warp/sample ----------
// 128-thread blocks (4 samples), 3 CTAs/SM (3 x 69632 B smem) -> 12 warps/SM.
#define ISTRIDE 272
#define IPLANE  8704          // 32 * 272
#define ISAMP   17408         // 2 planes

__global__ __launch_bounds__(128, 3)
void interact_kernel(const uint16_t* __restrict__ Hhi, const uint16_t* __restrict__ Hlo,
                     const float* __restrict__ emb, const int* __restrict__ sidx,
                     uint16_t* __restrict__ Ohi, uint16_t* __restrict__ Olo) {
    extern __shared__ __align__(16) uint8_t ism[];
    const int warp = threadIdx.x >> 5;
    const int lane = threadIdx.x & 31;
    const size_t s = (size_t)blockIdx.x * 4 + warp;
    uint8_t* my = ism + warp * ISAMP;
    const uint32_t base = smem_u32(my);

    int idx26[26];
#pragma unroll
    for (int v = 0; v < 26; v++) idx26[v] = sidx[s * 26 + v] & (VOCAB - 1);

    {
        uint2 hh = *(const uint2*)&Hhi[s * 128 + lane * 4];
        uint2 ll = *(const uint2*)&Hlo[s * 128 + lane * 4];
        *(uint2*)(my + lane * 8) = hh;
        *(uint2*)(my + IPLANE + lane * 8) = ll;
        *(uint2*)&Ohi[s * 512 + lane * 4] = hh;
        *(uint2*)&Olo[s * 512 + lane * 4] = ll;
    }
#pragma unroll
    for (int r = 27; r < 32; r++) {
        *(uint2*)(my + r * ISTRIDE + lane * 8) = make_uint2(0, 0);
        *(uint2*)(my + IPLANE + r * ISTRIDE + lane * 8) = make_uint2(0, 0);
    }

#pragma unroll
    for (int w0 = 0; w0 < 26; w0 += 8) {
        float4 e[8];
        const int cnt = (26 - w0 < 8) ? (26 - w0) : 8;
#pragma unroll
        for (int j = 0; j < 8; j++)
            if (j < cnt)
                e[j] = *(const float4*)&emb[(size_t)idx26[w0 + j] * 128 + lane * 4];
#pragma unroll
        for (int j = 0; j < 8; j++)
            if (j < cnt) {
                const int r = w0 + j + 1;
                float f[4] = {e[j].x, e[j].y, e[j].z, e[j].w};
                uint16_t h[4], l[4];
#pragma unroll
                for (int q = 0; q < 4; q++) f2hilo(f[q], h[q], l[q]);
                *(uint2*)(my + r * ISTRIDE + lane * 8) =
                    make_uint2((uint32_t)h[0] | ((uint32_t)h[1] << 16),
                               (uint32_t)h[2] | ((uint32_t)h[3] << 16));
                *(uint2*)(my + IPLANE + r * ISTRIDE + lane * 8) =
                    make_uint2((uint32_t)l[0] | ((uint32_t)l[1] << 16),
                               (uint32_t)l[2] | ((uint32_t)l[3] << 16));
            }
    }
    __syncwarp();

    float acc[2][4][4];
#pragma unroll
    for (int a = 0; a < 2; a++)
#pragma unroll
        for (int b = 0; b < 4; b++)
#pragma unroll
            for (int c = 0; c < 4; c++) acc[a][b][c] = 0.f;

    const uint32_t aoff = base + (uint32_t)(lane & 15) * ISTRIDE + (lane >> 4) * 16;
    const uint32_t boff = base + (uint32_t)((lane & 7) + ((lane >> 4) << 3)) * ISTRIDE
                        + (((lane >> 3) & 1) << 4);

#pragma unroll
    for (int ks = 0; ks < 8; ks++) {
        const uint32_t kb = ks * 32;
        uint32_t aH[2][4], aL[2][4], bB[2][4];
        ldsm4(aH[0], aoff + kb);
        ldsm4(aH[1], aoff + 16 * ISTRIDE + kb);
        ldsm4(aL[0], aoff + IPLANE + kb);
        ldsm4(aL[1], aoff + IPLANE + 16 * ISTRIDE + kb);
        ldsm4(bB[0], boff + kb);
        ldsm4(bB[1], boff + 16 * ISTRIDE + kb);
#pragma unroll
        for (int g = 0; g < 2; g++)
#pragma unroll
            for (int mt = 0; mt < 2; mt++) {
                mma_bf16(acc[mt][g * 2],     aH[mt], &bB[g][0]);
                mma_bf16(acc[mt][g * 2 + 1], aH[mt], &bB[g][2]);
            }
#pragma unroll
        for (int g = 0; g < 2; g++) {
#pragma unroll
            for (int mt = 0; mt < 2; mt++) {
                mma_bf16(acc[mt][g * 2],     aL[mt], &bB[g][0]);
                mma_bf16(acc[mt][g * 2 + 1], aL[mt], &bB[g][2]);
            }
            ldsm4(bB[g], boff + IPLANE + g * 16 * ISTRIDE + kb);
        }
#pragma unroll
        for (int g = 0; g < 2; g++)
#pragma unroll
            for (int mt = 0; mt < 2; mt++) {
                mma_bf16(acc[mt][g * 2],     aH[mt], &bB[g][0]);
                mma_bf16(acc[mt][g * 2 + 1], aH[mt], &bB[g][2]);
            }
    }

#pragma unroll
    for (int mt = 0; mt < 2; mt++)
#pragma unroll
        for (int nt = 0; nt < 4; nt++)
#pragma unroll
            for (int q = 0; q < 4; q++) {
                int i = mt * 16 + (lane >> 2) + ((q >> 1) << 3);
                int j = nt * 8 + (lane & 3) * 2 + (q & 1);
                if (i <= j && j < 27) {
                    int flat = 27 * i - (i * (i - 1)) / 2 + (j - i);
                    uint16_t h, l;
                    f2hilo(acc[mt][nt][q], h, l);
                    Ohi[s * 512 + 128 + flat] = h;
                    Olo[s * 512 + 128 + flat] = l;
                }
            }
    if (lane < 6) {
        Ohi[s * 512 + 506 + lane] = 0;
        Olo[s * 512 + 506 + lane] = 0;
    }
}

// ---------------- final 256 -> 1 dot (fp32 in) ----------------
__global__ void final_dot_kernel(const float* __restrict__ F, const float* __restrict__ w,
                                 const float* __restrict__ b, float* __restrict__ out) {
    const int warp = threadIdx.x >> 5;
    const int lane = threadIdx.x & 31;
    const size_t s = (size_t)blockIdx.x * 8 + warp;
    float acc = 0.f;
#pragma unroll
    for (int q = 0; q < 2; q++) {
        float4 x = *(const float4*)&F[s * 256 + lane * 8 + q * 4];
        acc += x.x * w[lane * 8 + q * 4]     + x.y * w[lane * 8 + q * 4 + 1]
             + x.z * w[lane * 8 + q * 4 + 2] + x.w * w[lane * 8 + q * 4 + 3];
    }
#pragma unroll
    for (int o = 16; o; o >>= 1) acc += __shfl_xor_sync(0xFFFFFFFFu, acc, o);
    if (lane == 0) out[s] = acc + b[0];
}

// ---------------- host launch ----------------
extern "C" void kernel_launch(void* const* d_in, const int* in_sizes, int n_in,
                              void* d_out, int out_size) {
    const float* dense = (const float*)d_in[0];
    const int*   sidx  = (const int*)d_in[1];
    const float* emb   = (const float*)d_in[2];
    const float* bw0 = (const float*)d_in[3];  const float* bb0 = (const float*)d_in[4];
    const float* bw1 = (const float*)d_in[5];  const float* bb1 = (const float*)d_in[6];
    const float* bw2 = (const float*)d_in[7];  const float* bb2 = (const float*)d_in[8];
    const float* tw0 = (const float*)d_in[9];  const float* tb0 = (const float*)d_in[10];
    const float* tw1 = (const float*)d_in[11]; const float* tb1 = (const float*)d_in[12];
    const float* tw2 = (const float*)d_in[13]; const float* tb2 = (const float*)d_in[14];
    const float* tw3 = (const float*)d_in[15]; const float* tb3 = (const float*)d_in[16];
    const float* tw4 = (const float*)d_in[17]; const float* tb4 = (const float*)d_in[18];

    uint16_t *bufAh, *bufAl, *bufBh, *bufBl, *wth, *wtl;
    float *fin;
    cudaGetSymbolAddress((void**)&bufAh, g_bufA_hi);
    cudaGetSymbolAddress((void**)&bufAl, g_bufA_lo);
    cudaGetSymbolAddress((void**)&bufBh, g_bufB_hi);
    cudaGetSymbolAddress((void**)&bufBl, g_bufB_lo);
    cudaGetSymbolAddress((void**)&wth, g_wt_hi);
    cudaGetSymbolAddress((void**)&wtl, g_wt_lo);
    cudaGetSymbolAddress((void**)&fin, g_fin);

    const int DSM = 3 * STAGE_B;       // 98304
    const int ISM = 4 * ISAMP;         // 69632
    cudaFuncSetAttribute(gemm_hmma, cudaFuncAttributeMaxDynamicSharedMemorySize, DSM);
    cudaFuncSetAttribute(interact_kernel, cudaFuncAttributeMaxDynamicSharedMemorySize, ISM);

    dim3 blk(256);
    dim3 iblk(128);

    // conversions (2 launches total)
    conv_dense_kernel<<<BATCH * 32 / 256, blk>>>(dense, bufAh, bufAl);
    conv_wt_all<<<1184, blk>>>(bw0, bw1, bw2, tw0, tw1, tw2, tw3, wth, wtl);

    // bottom MLP
    gemm_hmma<<<dim3(4, 512), blk, DSM>>>(bufAh, bufAl, wth + OFF_BW0, wtl + OFF_BW0, bb0, bufBh, bufBl, fin, 512, 32, 1, 0);
    gemm_hmma<<<dim3(2, 512), blk, DSM>>>(bufBh, bufBl, wth + OFF_BW1, wtl + OFF_BW1, bb1, bufAh, bufAl, fin, 256, 512, 1, 0);
    gemm_hmma<<<dim3(1, 512), blk, DSM>>>(bufAh, bufAl, wth + OFF_BW2, wtl + OFF_BW2, bb2, bufBh, bufBl, fin, 128, 256, 1, 0);

    // gather + interaction (HMMA gram, 3 CTAs/SM) -> [B, 512]
    interact_kernel<<<BATCH / 4, iblk, ISM>>>(bufBh, bufBl, emb, sidx, bufAh, bufAl);

    // top MLP
    gemm_hmma<<<dim3(8, 512), blk, DSM>>>(bufAh, bufAl, wth + OFF_TW0, wtl + OFF_TW0, tb0, bufBh, bufBl, fin, 1024, 512, 1, 0);
    gemm_hmma<<<dim3(8, 512), blk, DSM>>>(bufBh, bufBl, wth + OFF_TW1, wtl + OFF_TW1, tb1, bufAh, bufAl, fin, 1024, 1024, 1, 0);
    gemm_hmma<<<dim3(4, 512), blk, DSM>>>(bufAh, bufAl, wth + OFF_TW2, wtl + OFF_TW2, tb2, bufBh, bufBl, fin, 512, 1024, 1, 0);
    gemm_hmma<<<dim3(2, 512), blk, DSM>>>(bufBh, bufBl, wth + OFF_TW3, wtl + OFF_TW3, tb3, bufAh, bufAl, fin, 256, 512, 1, 1);

    // final 256 -> 1 (fp32 in)
    final_dot_kernel<<<BATCH / 8, blk>>>(fin, tw4, tb4, (float*)d_out);
}